// round 13
// baseline (speedup 1.0000x reference)
#include <cuda_runtime.h>
#include <cuda_bf16.h>
#include <cstdint>
#include <math.h>

#define BATCH 4
#define SEQ   4096
#define CDIM  1024
#define HEADS 16
#define HDIM  64
#define MROWS 16384
#define BH    64
#define NIT2  16            // K=1024, BK=64

// ---------------- scratch ----------------
__device__ float g_Af[(size_t)MROWS * CDIM];        // A permuted tf32 (frag-ready)
__device__ float g_Bq[(size_t)3072 * CDIM];         // W_qkv permuted tf32
__device__ float g_Bp[(size_t)CDIM * CDIM];         // W_proj permuted tf32
__device__ float g_q[(size_t)MROWS * CDIM];
__device__ float g_k[(size_t)MROWS * CDIM];
__device__ float g_v[(size_t)MROWS * CDIM];
__device__ float g_ctx[BH * HDIM * HDIM];
__device__ float g_colsum[BH * HDIM];

__device__ __forceinline__ uint32_t smem_u32(const void* p) {
    uint32_t a;
    asm("{ .reg .u64 t; cvta.to.shared.u64 t, %1; cvt.u32.u64 %0, t; }" : "=r"(a) : "l"(p));
    return a;
}
__device__ __forceinline__ void cpa16(uint32_t saddr, const void* g) {
    asm volatile("cp.async.cg.shared.global [%0], [%1], 16;" :: "r"(saddr), "l"(g));
}
#define CPA_COMMIT() asm volatile("cp.async.commit_group;" ::: "memory")

__device__ __forceinline__ uint32_t tf32r(float f) {
    uint32_t u;
    asm("cvt.rna.tf32.f32 %0, %1;" : "=r"(u) : "f"(f));
    return u;
}
__device__ __forceinline__ void mma_tf32(float* d, const uint4 a, const uint2 b) {
    asm volatile("mma.sync.aligned.m16n8k8.row.col.f32.tf32.tf32.f32 "
        "{%0,%1,%2,%3}, {%4,%5,%6,%7}, {%8,%9}, {%0,%1,%2,%3};"
        : "+f"(d[0]), "+f"(d[1]), "+f"(d[2]), "+f"(d[3])
        : "r"(a.x), "r"(a.y), "r"(a.z), "r"(a.w), "r"(b.x), "r"(b.y));
}

// ---------------- TF32 GEMM: A via smem (BK=64, 3-stage), B direct LDG ----------------
// A permuted: [mblk][kblk][lane] uint4 ; B permuted: [nblk][kblk][lane] uint2.
// CTA 128x128, 256 thr, warp tile 64x32. Stage = A-only 32KB.
#define STGB  32768
#define GSMEM (3 * STGB)    // 98304 -> 2 CTA/SM

__device__ __forceinline__ void load_stage_a(uint32_t dst,
        const float* __restrict__ A, int it, int bmblk, int tid) {
    const int kb0 = it * 8;
#pragma unroll
    for (int l = 0; l < 8; l++) {
        int c = tid + l * 256;
        int mb = c >> 8, rest = c & 255;        // rest = kbl*32 + lane
        cpa16(dst + (uint32_t)c * 16,
              A + ((size_t)(bmblk + mb) * 128 + kb0) * 128 + rest * 4);
    }
    CPA_COMMIT();
}

template<int MODE>
__global__ void __launch_bounds__(256)
gemm_tf32(const float* __restrict__ A, const float* __restrict__ Bm,
          const float* __restrict__ bias, float* __restrict__ Cout, int Nn)
{
    extern __shared__ char dsm[];
    const uint32_t s0 = smem_u32(dsm);

    const int tid = threadIdx.x, wid = tid >> 5, lane = tid & 31;
    const int bm = blockIdx.y * 128, bn = blockIdx.x * 128;
    const int bmblk = bm >> 4, bnblk = bn >> 3;
    const int mw = wid & 1, nw = wid >> 1;      // warp tile 64x32

    float acc[4][4][4];
#pragma unroll
    for (int i = 0; i < 4; i++)
#pragma unroll
        for (int j = 0; j < 4; j++)
#pragma unroll
            for (int r = 0; r < 4; r++) acc[i][j][r] = 0.f;

    load_stage_a(s0,        A, 0, bmblk, tid);
    load_stage_a(s0 + STGB, A, 1, bmblk, tid);

    // per-warp B base (uint2 units), lane folded in
    const uint2* bbase = (const uint2*)Bm + ((size_t)(bnblk + nw * 4) * 128) * 32 + lane;

    for (int i = 0; i < NIT2; i++) {
        if (i + 2 < NIT2) asm volatile("cp.async.wait_group 1;" ::: "memory");
        else              asm volatile("cp.async.wait_group 0;" ::: "memory");
        __syncthreads();
        if (i + 2 < NIT2)
            load_stage_a(s0 + ((i + 2) % 3) * STGB, A, i + 2, bmblk, tid);

        const uint4* apw = (const uint4*)(dsm + (i % 3) * STGB) + (mw * 4) * 8 * 32 + lane;
        const uint2* bpw = bbase + (size_t)(i * 8) * 32;
#pragma unroll
        for (int kc = 0; kc < 8; kc++) {
            uint2 bf[4];
#pragma unroll
            for (int nt = 0; nt < 4; nt++)
                bf[nt] = bpw[(size_t)nt * 4096 + kc * 32];   // nt*128*32
            uint4 af[4];
#pragma unroll
            for (int mt = 0; mt < 4; mt++)
                af[mt] = apw[(mt * 8 + kc) * 32];
#pragma unroll
            for (int mt = 0; mt < 4; mt++)
#pragma unroll
                for (int nt = 0; nt < 4; nt++)
                    mma_tf32(acc[mt][nt], af[mt], bf[nt]);
        }
    }

    const int mbase = mw * 64, nbase = nw * 32;
    const int r0 = lane >> 2, cpair = (lane & 3) * 2;
#pragma unroll
    for (int mt = 0; mt < 4; mt++) {
#pragma unroll
        for (int nt = 0; nt < 4; nt++) {
            int col = bn + nbase + nt * 8 + cpair;
            float bv0 = bias[col], bv1 = bias[col + 1];
            int m0 = bm + mbase + mt * 16 + r0;
            float2 v0 = make_float2(acc[mt][nt][0] + bv0, acc[mt][nt][1] + bv1);
            float2 v1 = make_float2(acc[mt][nt][2] + bv0, acc[mt][nt][3] + bv1);
            if (MODE == 0) {
                *(float2*)&Cout[(size_t)m0 * Nn + col] = v0;
                *(float2*)&Cout[(size_t)(m0 + 8) * Nn + col] = v1;
            } else {
                int s = col >> 10, rem = col & 1023;
                int h = rem >> 6, dd = rem & 63;
                float* dst = (s == 0) ? g_q : (s == 1) ? g_k : g_v;
                {
                    int b = m0 >> 12, n = m0 & 4095;
                    *(float2*)&dst[(((size_t)(b * HEADS + h) * SEQ + n) << 6) + dd] = v0;
                }
                {
                    int m1 = m0 + 8, b = m1 >> 12, n = m1 & 4095;
                    *(float2*)&dst[(((size_t)(b * HEADS + h) * SEQ + n) << 6) + dd] = v1;
                }
            }
        }
    }
}

// ---------------- conversions (unchanged) ----------------
__global__ void __launch_bounds__(256) convA(const float* __restrict__ src,
                                             float* __restrict__ dst) {
    int w = blockIdx.x * 8 + (threadIdx.x >> 5);
    int lane = threadIdx.x & 31;
    int mb = w >> 7, kb = w & 127;
    int r = lane >> 2, c = lane & 3;
    const float* p = src + (size_t)(mb * 16) * CDIM + kb * 8;
    uint4 o;
    o.x = tf32r(p[(size_t)r * CDIM + c]);
    o.y = tf32r(p[(size_t)(r + 8) * CDIM + c]);
    o.z = tf32r(p[(size_t)r * CDIM + c + 4]);
    o.w = tf32r(p[(size_t)(r + 8) * CDIM + c + 4]);
    ((uint4*)dst)[((size_t)mb * 128 + kb) * 32 + lane] = o;
}

__global__ void __launch_bounds__(256) convWT(const float* __restrict__ W,
                                              float* __restrict__ dst, int N) {
    int w = blockIdx.x * 8 + (threadIdx.x >> 5);
    int lane = threadIdx.x & 31;
    int nb = w >> 7, kb = w & 127;
    int g = lane >> 2, c = lane & 3;
    const float* p = W + (size_t)(kb * 8) * N + nb * 8 + g;
    uint2 o;
    o.x = tf32r(p[(size_t)c * N]);
    o.y = tf32r(p[(size_t)(c + 4) * N]);
    ((uint2*)dst)[((size_t)nb * 128 + kb) * 32 + lane] = o;
}

// ---------------- middle: exp(k)^T v + colsum via tf32 MMA (unchanged) ----------------
__global__ void __launch_bounds__(256) ctx_mma() {
    const int bh = blockIdx.y, chunk = blockIdx.x;
    const float* kp = g_k + (size_t)bh * SEQ * HDIM;
    const float* vp = g_v + (size_t)bh * SEQ * HDIM;
    __shared__ float kt[32][72], vt[32][72];
    __shared__ float csred[256];
    const int tid = threadIdx.x, warp = tid >> 5, lane = tid & 31;
    const int mt = warp >> 1;
    const int ng = (warp & 1) * 4;
    const int fr = lane >> 2, fc = lane & 3;

    float acc[4][4];
#pragma unroll
    for (int i = 0; i < 4; i++)
#pragma unroll
        for (int j = 0; j < 4; j++) acc[i][j] = 0.f;
    float csum = 0.f;
    const int n0 = chunk * 256;

    for (int t = 0; t < 8; t++) {
        __syncthreads();
        for (int i = tid; i < 2048; i += 256) {
            int r = i >> 6, c = i & 63;
            size_t g = (size_t)(n0 + t * 32 + r) * 64 + c;
            float ex = __expf(kp[g]);
            kt[r][c] = ex;
            csum += ex;
            vt[r][c] = vp[g];
        }
        __syncthreads();
#pragma unroll
        for (int ks = 0; ks < 4; ks++) {
            const int nr = ks * 8;
            uint4 af;
            af.x = tf32r(kt[nr + fc][mt * 16 + fr]);
            af.y = tf32r(kt[nr + fc][mt * 16 + fr + 8]);
            af.z = tf32r(kt[nr + fc + 4][mt * 16 + fr]);
            af.w = tf32r(kt[nr + fc + 4][mt * 16 + fr + 8]);
#pragma unroll
            for (int nt = 0; nt < 4; nt++) {
                const int e0 = (ng + nt) * 8;
                uint2 bf;
                bf.x = tf32r(vt[nr + fc][e0 + fr]);
                bf.y = tf32r(vt[nr + fc + 4][e0 + fr]);
                mma_tf32(acc[nt], af, bf);
            }
        }
    }

    const int row = lane >> 2, colp = (lane & 3) * 2;
    const int d0 = mt * 16;
#pragma unroll
    for (int nt = 0; nt < 4; nt++) {
        int e = (ng + nt) * 8 + colp;
        float* base = &g_ctx[((size_t)bh * 64 + d0 + row) * 64 + e];
        atomicAdd(base,     acc[nt][0]);
        atomicAdd(base + 1, acc[nt][1]);
        float* base2 = &g_ctx[((size_t)bh * 64 + d0 + row + 8) * 64 + e];
        atomicAdd(base2,     acc[nt][2]);
        atomicAdd(base2 + 1, acc[nt][3]);
    }
    csred[tid] = csum;
    __syncthreads();
    if (tid < 64)
        atomicAdd(&g_colsum[bh * 64 + tid],
                  csred[tid] + csred[tid + 64] + csred[tid + 128] + csred[tid + 192]);
}

// ---------------- softmax_D(q) @ ctx via tf32 MMA -> permuted tf32 g_Af (unchanged) ----------------
__global__ void __launch_bounds__(256) qattend() {
    const int bh = blockIdx.y;
    __shared__ float ctxs[64][72];
    __shared__ float rsum[64];
    __shared__ float pb[32][68];
    __shared__ float sout[32][68];
    const int tid = threadIdx.x;
    if (tid < 64) rsum[tid] = 1.f / g_colsum[bh * 64 + tid];
    __syncthreads();
    for (int i = tid; i < 4096; i += 256) {
        int d = i >> 6, ee = i & 63;
        ctxs[d][ee] = g_ctx[((size_t)bh * 64 + d) * 64 + ee] * rsum[d];
    }
    const int warp = tid >> 5, lane = tid & 31;
    const int b = bh >> 4, h = bh & 15;

#pragma unroll
    for (int rr = 0; rr < 4; rr++) {
        int lr = warp * 4 + rr;
        int n = blockIdx.x * 32 + lr;
        const float* qrow = g_q + ((size_t)bh * SEQ + n) * 64;
        float q0 = qrow[lane], q1 = qrow[lane + 32];
        float mx = fmaxf(q0, q1);
#pragma unroll
        for (int o = 16; o; o >>= 1) mx = fmaxf(mx, __shfl_xor_sync(0xffffffffu, mx, o));
        float e0 = __expf(q0 - mx), e1 = __expf(q1 - mx);
        float s = e0 + e1;
#pragma unroll
        for (int o = 16; o; o >>= 1) s += __shfl_xor_sync(0xffffffffu, s, o);
        float inv = 1.f / s;
        pb[lr][lane] = e0 * inv;
        pb[lr][lane + 32] = e1 * inv;
    }
    __syncthreads();

    const int mt = warp >> 2;
    const int ngrp = warp & 3;
    const int fr = lane >> 2, fc = lane & 3;
    float acc[2][4] = {{0.f, 0.f, 0.f, 0.f}, {0.f, 0.f, 0.f, 0.f}};
#pragma unroll
    for (int ks = 0; ks < 8; ks++) {
        const int k0 = ks * 8;
        uint4 af;
        af.x = tf32r(pb[mt * 16 + fr][k0 + fc]);
        af.y = tf32r(pb[mt * 16 + fr + 8][k0 + fc]);
        af.z = tf32r(pb[mt * 16 + fr][k0 + fc + 4]);
        af.w = tf32r(pb[mt * 16 + fr + 8][k0 + fc + 4]);
#pragma unroll
        for (int nt = 0; nt < 2; nt++) {
            const int e0 = (ngrp * 2 + nt) * 8;
            uint2 bf;
            bf.x = tf32r(ctxs[k0 + fc][e0 + fr]);
            bf.y = tf32r(ctxs[k0 + fc + 4][e0 + fr]);
            mma_tf32(acc[nt], af, bf);
        }
    }
    const int row = lane >> 2, colp = (lane & 3) * 2;
#pragma unroll
    for (int nt = 0; nt < 2; nt++) {
        const int e = (ngrp * 2 + nt) * 8 + colp;
        sout[mt * 16 + row][e] = acc[nt][0];
        sout[mt * 16 + row][e + 1] = acc[nt][1];
        sout[mt * 16 + row + 8][e] = acc[nt][2];
        sout[mt * 16 + row + 8][e + 1] = acc[nt][3];
    }
    __syncthreads();

    const int mblk0 = (b * SEQ + blockIdx.x * 32) >> 4;
    const int r = lane >> 2, c = lane & 3;
#pragma unroll
    for (int t = 0; t < 2; t++) {
        int idx = warp * 2 + t;
        int mb = idx >> 3, kb = idx & 7;
        uint4 o;
        o.x = tf32r(sout[mb * 16 + r][kb * 8 + c]);
        o.y = tf32r(sout[mb * 16 + r + 8][kb * 8 + c]);
        o.z = tf32r(sout[mb * 16 + r][kb * 8 + c + 4]);
        o.w = tf32r(sout[mb * 16 + r + 8][kb * 8 + c + 4]);
        ((uint4*)g_Af)[((size_t)(mblk0 + mb) * 128 + (h * 8 + kb)) * 32 + lane] = o;
    }
}

// ---------------------------------------------------------------------------
extern "C" void kernel_launch(void* const* d_in, const int* in_sizes, int n_in,
                              void* d_out, int out_size) {
    const float* x      = (const float*)d_in[0];
    const float* W_qkv  = (const float*)d_in[1];
    const float* b_qkv  = (const float*)d_in[2];
    const float* W_proj = (const float*)d_in[3];
    const float* b_proj = (const float*)d_in[4];
    float* out = (float*)d_out;

    void *paf, *pbq, *pbp, *pctx, *pcs;
    cudaGetSymbolAddress(&paf,  g_Af);
    cudaGetSymbolAddress(&pbq,  g_Bq);
    cudaGetSymbolAddress(&pbp,  g_Bp);
    cudaGetSymbolAddress(&pctx, g_ctx);
    cudaGetSymbolAddress(&pcs,  g_colsum);

    cudaFuncSetAttribute(gemm_tf32<0>, cudaFuncAttributeMaxDynamicSharedMemorySize, GSMEM);
    cudaFuncSetAttribute(gemm_tf32<1>, cudaFuncAttributeMaxDynamicSharedMemorySize, GSMEM);

    convA<<<(MROWS / 16) * (CDIM / 8) / 8, 256>>>(x, (float*)paf);
    convWT<<<(3072 / 8) * 128 / 8, 256>>>(W_qkv, (float*)pbq, 3072);
    convWT<<<(CDIM / 8) * 128 / 8, 256>>>(W_proj, (float*)pbp, CDIM);
    cudaMemsetAsync(pctx, 0, (size_t)BH * HDIM * HDIM * sizeof(float));
    cudaMemsetAsync(pcs,  0, (size_t)BH * HDIM * sizeof(float));

    gemm_tf32<1><<<dim3(3072 / 128, MROWS / 128), 256, GSMEM>>>(
        (const float*)paf, (const float*)pbq, b_qkv, nullptr, 3072);

    ctx_mma<<<dim3(SEQ / 256, BH), 256>>>();
    qattend<<<dim3(SEQ / 32, BH), 256>>>();

    gemm_tf32<0><<<dim3(CDIM / 128, MROWS / 128), 256, GSMEM>>>(
        (const float*)paf, (const float*)pbp, b_proj, out, CDIM);
}

// round 14
// speedup vs baseline: 1.6349x; 1.6349x over previous
#include <cuda_runtime.h>
#include <cuda_bf16.h>
#include <cstdint>
#include <math.h>

#define BATCH 4
#define SEQ   4096
#define CDIM  1024
#define HEADS 16
#define HDIM  64
#define MROWS 16384
#define BH    64
#define NIT   32            // K=1024, BK=32

// ---------------- scratch ----------------
__device__ float g_Af[(size_t)MROWS * CDIM];        // A permuted tf32 (frag-ready)
__device__ float g_Bq[(size_t)3072 * CDIM];         // W_qkv permuted tf32
__device__ float g_Bp[(size_t)CDIM * CDIM];         // W_proj permuted tf32
__device__ float g_q[(size_t)MROWS * CDIM];
__device__ float g_k[(size_t)MROWS * CDIM];
__device__ float g_v[(size_t)MROWS * CDIM];
__device__ float g_ctx[BH * HDIM * HDIM];
__device__ float g_colsum[BH * HDIM];

__device__ __forceinline__ uint32_t smem_u32(const void* p) {
    uint32_t a;
    asm("{ .reg .u64 t; cvta.to.shared.u64 t, %1; cvt.u32.u64 %0, t; }" : "=r"(a) : "l"(p));
    return a;
}
__device__ __forceinline__ void cpa16(uint32_t saddr, const void* g) {
    asm volatile("cp.async.cg.shared.global [%0], [%1], 16;" :: "r"(saddr), "l"(g));
}
#define CPA_COMMIT() asm volatile("cp.async.commit_group;" ::: "memory")

__device__ __forceinline__ uint32_t tf32r(float f) {
    uint32_t u;
    asm("cvt.rna.tf32.f32 %0, %1;" : "=r"(u) : "f"(f));
    return u;
}
__device__ __forceinline__ void mma_tf32(float* d, const uint4 a, const uint2 b) {
    asm volatile("mma.sync.aligned.m16n8k8.row.col.f32.tf32.tf32.f32 "
        "{%0,%1,%2,%3}, {%4,%5,%6,%7}, {%8,%9}, {%0,%1,%2,%3};"
        : "+f"(d[0]), "+f"(d[1]), "+f"(d[2]), "+f"(d[3])
        : "r"(a.x), "r"(a.y), "r"(a.z), "r"(a.w), "r"(b.x), "r"(b.y));
}

// ---------------- TF32 GEMM (R12, proven: 128x128, BK=32, 3-stage) ----------------
#define ASTG  16384
#define STGB  32768
#define GSMEM (3 * STGB)    // 98304 -> 2 CTA/SM

__device__ __forceinline__ void load_stage(uint32_t dst,
        const float* __restrict__ A, const float* __restrict__ B,
        int it, int bmblk, int bnblk, int tid) {
    const int kb0 = it * 4;
#pragma unroll
    for (int l = 0; l < 4; l++) {
        int c = tid + l * 256;
        int mb = c >> 7, rest = c & 127;
        cpa16(dst + (uint32_t)(mb * 2048 + rest * 16),
              A + ((size_t)(bmblk + mb) * 128 + kb0) * 128 + rest * 4);
    }
#pragma unroll
    for (int l = 0; l < 4; l++) {
        int c = tid + l * 256;
        int nb = c >> 6, rest = c & 63;
        cpa16(dst + ASTG + (uint32_t)(nb * 1024 + rest * 16),
              B + ((size_t)(bnblk + nb) * 128 + kb0) * 64 + rest * 4);
    }
    CPA_COMMIT();
}

template<int MODE>
__global__ void __launch_bounds__(256)
gemm_tf32(const float* __restrict__ A, const float* __restrict__ Bm,
          const float* __restrict__ bias, float* __restrict__ Cout, int Nn)
{
    extern __shared__ char dsm[];
    const uint32_t s0 = smem_u32(dsm);

    const int tid = threadIdx.x, wid = tid >> 5, lane = tid & 31;
    const int bm = blockIdx.y * 128, bn = blockIdx.x * 128;
    const int bmblk = bm >> 4, bnblk = bn >> 3;
    const int mw = wid & 1, nw = wid >> 1;

    float acc[4][4][4];
#pragma unroll
    for (int i = 0; i < 4; i++)
#pragma unroll
        for (int j = 0; j < 4; j++)
#pragma unroll
            for (int r = 0; r < 4; r++) acc[i][j][r] = 0.f;

    load_stage(s0,        A, Bm, 0, bmblk, bnblk, tid);
    load_stage(s0 + STGB, A, Bm, 1, bmblk, bnblk, tid);

    for (int i = 0; i < NIT; i++) {
        if (i + 2 < NIT) asm volatile("cp.async.wait_group 1;" ::: "memory");
        else             asm volatile("cp.async.wait_group 0;" ::: "memory");
        __syncthreads();
        if (i + 2 < NIT)
            load_stage(s0 + ((i + 2) % 3) * STGB, A, Bm, i + 2, bmblk, bnblk, tid);

        const uint4* apw = (const uint4*)(dsm + (i % 3) * STGB) + mw * 16 * 32 + lane;
        const uint2* bpw = (const uint2*)(dsm + (i % 3) * STGB + ASTG) + nw * 16 * 32 + lane;
#pragma unroll
        for (int kc = 0; kc < 4; kc++) {
            uint4 af[4];
            uint2 bf[4];
#pragma unroll
            for (int mt = 0; mt < 4; mt++)
                af[mt] = apw[(mt * 4 + kc) * 32];
#pragma unroll
            for (int nt = 0; nt < 4; nt++)
                bf[nt] = bpw[(nt * 4 + kc) * 32];
#pragma unroll
            for (int mt = 0; mt < 4; mt++)
#pragma unroll
                for (int nt = 0; nt < 4; nt++)
                    mma_tf32(acc[mt][nt], af[mt], bf[nt]);
        }
    }

    const int mbase = mw * 64, nbase = nw * 32;
    const int r0 = lane >> 2, cpair = (lane & 3) * 2;
#pragma unroll
    for (int mt = 0; mt < 4; mt++) {
#pragma unroll
        for (int nt = 0; nt < 4; nt++) {
            int col = bn + nbase + nt * 8 + cpair;
            float bv0 = bias[col], bv1 = bias[col + 1];
            int m0 = bm + mbase + mt * 16 + r0;
            float2 v0 = make_float2(acc[mt][nt][0] + bv0, acc[mt][nt][1] + bv1);
            float2 v1 = make_float2(acc[mt][nt][2] + bv0, acc[mt][nt][3] + bv1);
            if (MODE == 0) {
                *(float2*)&Cout[(size_t)m0 * Nn + col] = v0;
                *(float2*)&Cout[(size_t)(m0 + 8) * Nn + col] = v1;
            } else {
                int s = col >> 10, rem = col & 1023;
                int h = rem >> 6, dd = rem & 63;
                float* dst = (s == 0) ? g_q : (s == 1) ? g_k : g_v;
                {
                    int b = m0 >> 12, n = m0 & 4095;
                    *(float2*)&dst[(((size_t)(b * HEADS + h) * SEQ + n) << 6) + dd] = v0;
                }
                {
                    int m1 = m0 + 8, b = m1 >> 12, n = m1 & 4095;
                    *(float2*)&dst[(((size_t)(b * HEADS + h) * SEQ + n) << 6) + dd] = v1;
                }
            }
        }
    }
}

// ---------------- merged prep: A-permute | Wqkv-permute | Wproj-permute | zeroing ----------------
// block ranges:
//  [0, 16384)               convA   (x -> g_Af)
//  [16384, 22528)           convWT  (W_qkv -> g_Bq, N=3072)
//  [22528, 24576)           convWT  (W_proj -> g_Bp, N=1024)
//  [24576, 24832)           zero g_ctx   (256 blocks x 1024 floats via float4)
//  [24832]                  zero g_colsum (4096 floats)
#define PREP_A   16384
#define PREP_BQ  (PREP_A + 6144)
#define PREP_BP  (PREP_BQ + 2048)
#define PREP_Z1  (PREP_BP + 256)
#define PREP_N   (PREP_Z1 + 1)

__global__ void __launch_bounds__(256)
prep(const float* __restrict__ x, const float* __restrict__ Wq,
     const float* __restrict__ Wp)
{
    const int bx = blockIdx.x;
    const int warp = threadIdx.x >> 5, lane = threadIdx.x & 31;
    if (bx < PREP_A) {
        // A permute: tile per warp
        int w = bx * 8 + warp;
        int mb = w >> 7, kb = w & 127;
        int r = lane >> 2, c = lane & 3;
        const float* p = x + (size_t)(mb * 16) * CDIM + kb * 8;
        uint4 o;
        o.x = tf32r(p[(size_t)r * CDIM + c]);
        o.y = tf32r(p[(size_t)(r + 8) * CDIM + c]);
        o.z = tf32r(p[(size_t)r * CDIM + c + 4]);
        o.w = tf32r(p[(size_t)(r + 8) * CDIM + c + 4]);
        ((uint4*)g_Af)[((size_t)mb * 128 + kb) * 32 + lane] = o;
    } else if (bx < PREP_BQ) {
        int w = (bx - PREP_A) * 8 + warp;
        int nb = w >> 7, kb = w & 127;
        int g = lane >> 2, c = lane & 3;
        const float* p = Wq + (size_t)(kb * 8) * 3072 + nb * 8 + g;
        uint2 o;
        o.x = tf32r(p[(size_t)c * 3072]);
        o.y = tf32r(p[(size_t)(c + 4) * 3072]);
        ((uint2*)g_Bq)[((size_t)nb * 128 + kb) * 32 + lane] = o;
    } else if (bx < PREP_BP) {
        int w = (bx - PREP_BQ) * 8 + warp;
        int nb = w >> 7, kb = w & 127;
        int g = lane >> 2, c = lane & 3;
        const float* p = Wp + (size_t)(kb * 8) * CDIM + nb * 8 + g;
        uint2 o;
        o.x = tf32r(p[(size_t)c * CDIM]);
        o.y = tf32r(p[(size_t)(c + 4) * CDIM]);
        ((uint2*)g_Bp)[((size_t)nb * 128 + kb) * 32 + lane] = o;
    } else if (bx < PREP_Z1) {
        int i = (bx - PREP_BP) * 256 + threadIdx.x;     // float4 index
        ((float4*)g_ctx)[i] = make_float4(0.f, 0.f, 0.f, 0.f);
    } else {
        int i = threadIdx.x;                             // 1024 float4 over 256 thr
#pragma unroll
        for (int t = 0; t < 4; t++)
            ((float4*)g_colsum)[i + t * 256] = make_float4(0.f, 0.f, 0.f, 0.f);
    }
}

// ---------------- middle: exp(k)^T v + colsum via tf32 MMA (unchanged) ----------------
__global__ void __launch_bounds__(256) ctx_mma() {
    const int bh = blockIdx.y, chunk = blockIdx.x;
    const float* kp = g_k + (size_t)bh * SEQ * HDIM;
    const float* vp = g_v + (size_t)bh * SEQ * HDIM;
    __shared__ float kt[32][72], vt[32][72];
    __shared__ float csred[256];
    const int tid = threadIdx.x, warp = tid >> 5, lane = tid & 31;
    const int mt = warp >> 1;
    const int ng = (warp & 1) * 4;
    const int fr = lane >> 2, fc = lane & 3;

    float acc[4][4];
#pragma unroll
    for (int i = 0; i < 4; i++)
#pragma unroll
        for (int j = 0; j < 4; j++) acc[i][j] = 0.f;
    float csum = 0.f;
    const int n0 = chunk * 256;

    for (int t = 0; t < 8; t++) {
        __syncthreads();
        for (int i = tid; i < 2048; i += 256) {
            int r = i >> 6, c = i & 63;
            size_t g = (size_t)(n0 + t * 32 + r) * 64 + c;
            float ex = __expf(kp[g]);
            kt[r][c] = ex;
            csum += ex;
            vt[r][c] = vp[g];
        }
        __syncthreads();
#pragma unroll
        for (int ks = 0; ks < 4; ks++) {
            const int nr = ks * 8;
            uint4 af;
            af.x = tf32r(kt[nr + fc][mt * 16 + fr]);
            af.y = tf32r(kt[nr + fc][mt * 16 + fr + 8]);
            af.z = tf32r(kt[nr + fc + 4][mt * 16 + fr]);
            af.w = tf32r(kt[nr + fc + 4][mt * 16 + fr + 8]);
#pragma unroll
            for (int nt = 0; nt < 4; nt++) {
                const int e0 = (ng + nt) * 8;
                uint2 bf;
                bf.x = tf32r(vt[nr + fc][e0 + fr]);
                bf.y = tf32r(vt[nr + fc + 4][e0 + fr]);
                mma_tf32(acc[nt], af, bf);
            }
        }
    }

    const int row = lane >> 2, colp = (lane & 3) * 2;
    const int d0 = mt * 16;
#pragma unroll
    for (int nt = 0; nt < 4; nt++) {
        int e = (ng + nt) * 8 + colp;
        float* base = &g_ctx[((size_t)bh * 64 + d0 + row) * 64 + e];
        atomicAdd(base,     acc[nt][0]);
        atomicAdd(base + 1, acc[nt][1]);
        float* base2 = &g_ctx[((size_t)bh * 64 + d0 + row + 8) * 64 + e];
        atomicAdd(base2,     acc[nt][2]);
        atomicAdd(base2 + 1, acc[nt][3]);
    }
    csred[tid] = csum;
    __syncthreads();
    if (tid < 64)
        atomicAdd(&g_colsum[bh * 64 + tid],
                  csred[tid] + csred[tid + 64] + csred[tid + 128] + csred[tid + 192]);
}

// ---------------- softmax_D(q) @ ctx via tf32 MMA -> permuted tf32 g_Af (unchanged) ----------------
__global__ void __launch_bounds__(256) qattend() {
    const int bh = blockIdx.y;
    __shared__ float ctxs[64][72];
    __shared__ float rsum[64];
    __shared__ float pb[32][68];
    __shared__ float sout[32][68];
    const int tid = threadIdx.x;
    if (tid < 64) rsum[tid] = 1.f / g_colsum[bh * 64 + tid];
    __syncthreads();
    for (int i = tid; i < 4096; i += 256) {
        int d = i >> 6, ee = i & 63;
        ctxs[d][ee] = g_ctx[((size_t)bh * 64 + d) * 64 + ee] * rsum[d];
    }
    const int warp = tid >> 5, lane = tid & 31;
    const int b = bh >> 4, h = bh & 15;

#pragma unroll
    for (int rr = 0; rr < 4; rr++) {
        int lr = warp * 4 + rr;
        int n = blockIdx.x * 32 + lr;
        const float* qrow = g_q + ((size_t)bh * SEQ + n) * 64;
        float q0 = qrow[lane], q1 = qrow[lane + 32];
        float mx = fmaxf(q0, q1);
#pragma unroll
        for (int o = 16; o; o >>= 1) mx = fmaxf(mx, __shfl_xor_sync(0xffffffffu, mx, o));
        float e0 = __expf(q0 - mx), e1 = __expf(q1 - mx);
        float s = e0 + e1;
#pragma unroll
        for (int o = 16; o; o >>= 1) s += __shfl_xor_sync(0xffffffffu, s, o);
        float inv = 1.f / s;
        pb[lr][lane] = e0 * inv;
        pb[lr][lane + 32] = e1 * inv;
    }
    __syncthreads();

    const int mt = warp >> 2;
    const int ngrp = warp & 3;
    const int fr = lane >> 2, fc = lane & 3;
    float acc[2][4] = {{0.f, 0.f, 0.f, 0.f}, {0.f, 0.f, 0.f, 0.f}};
#pragma unroll
    for (int ks = 0; ks < 8; ks++) {
        const int k0 = ks * 8;
        uint4 af;
        af.x = tf32r(pb[mt * 16 + fr][k0 + fc]);
        af.y = tf32r(pb[mt * 16 + fr + 8][k0 + fc]);
        af.z = tf32r(pb[mt * 16 + fr][k0 + fc + 4]);
        af.w = tf32r(pb[mt * 16 + fr + 8][k0 + fc + 4]);
#pragma unroll
        for (int nt = 0; nt < 2; nt++) {
            const int e0 = (ngrp * 2 + nt) * 8;
            uint2 bf;
            bf.x = tf32r(ctxs[k0 + fc][e0 + fr]);
            bf.y = tf32r(ctxs[k0 + fc + 4][e0 + fr]);
            mma_tf32(acc[nt], af, bf);
        }
    }
    const int row = lane >> 2, colp = (lane & 3) * 2;
#pragma unroll
    for (int nt = 0; nt < 2; nt++) {
        const int e = (ngrp * 2 + nt) * 8 + colp;
        sout[mt * 16 + row][e] = acc[nt][0];
        sout[mt * 16 + row][e + 1] = acc[nt][1];
        sout[mt * 16 + row + 8][e] = acc[nt][2];
        sout[mt * 16 + row + 8][e + 1] = acc[nt][3];
    }
    __syncthreads();

    const int mblk0 = (b * SEQ + blockIdx.x * 32) >> 4;
    const int r = lane >> 2, c = lane & 3;
#pragma unroll
    for (int t = 0; t < 2; t++) {
        int idx = warp * 2 + t;
        int mb = idx >> 3, kb = idx & 7;
        uint4 o;
        o.x = tf32r(sout[mb * 16 + r][kb * 8 + c]);
        o.y = tf32r(sout[mb * 16 + r + 8][kb * 8 + c]);
        o.z = tf32r(sout[mb * 16 + r][kb * 8 + c + 4]);
        o.w = tf32r(sout[mb * 16 + r + 8][kb * 8 + c + 4]);
        ((uint4*)g_Af)[((size_t)(mblk0 + mb) * 128 + (h * 8 + kb)) * 32 + lane] = o;
    }
}

// ---------------------------------------------------------------------------
extern "C" void kernel_launch(void* const* d_in, const int* in_sizes, int n_in,
                              void* d_out, int out_size) {
    const float* x      = (const float*)d_in[0];
    const float* W_qkv  = (const float*)d_in[1];
    const float* b_qkv  = (const float*)d_in[2];
    const float* W_proj = (const float*)d_in[3];
    const float* b_proj = (const float*)d_in[4];
    float* out = (float*)d_out;

    void *paf, *pbq, *pbp;
    cudaGetSymbolAddress(&paf, g_Af);
    cudaGetSymbolAddress(&pbq, g_Bq);
    cudaGetSymbolAddress(&pbp, g_Bp);

    cudaFuncSetAttribute(gemm_tf32<0>, cudaFuncAttributeMaxDynamicSharedMemorySize, GSMEM);
    cudaFuncSetAttribute(gemm_tf32<1>, cudaFuncAttributeMaxDynamicSharedMemorySize, GSMEM);

    // 1) merged prep: permutes + zeroing in one launch
    prep<<<PREP_N, 256>>>(x, W_qkv, W_proj);

    // 2) qkv GEMM (tf32), scatter to q/k/v
    gemm_tf32<1><<<dim3(3072 / 128, MROWS / 128), 256, GSMEM>>>(
        (const float*)paf, (const float*)pbq, b_qkv, nullptr, 3072);

    // 3) ctx = exp(k)^T v, colsum
    ctx_mma<<<dim3(SEQ / 256, BH), 256>>>();

    // 4) attn = softmax_D(q) @ (ctx/colsum) -> permuted tf32 g_Af
    qattend<<<dim3(SEQ / 32, BH), 256>>>();

    // 5) proj GEMM
    gemm_tf32<0><<<dim3(CDIM / 128, MROWS / 128), 256, GSMEM>>>(
        (const float*)paf, (const float*)pbp, b_proj, out, CDIM);
}

// round 15
// speedup vs baseline: 1.6965x; 1.0377x over previous
#include <cuda_runtime.h>
#include <cuda_bf16.h>
#include <cstdint>
#include <math.h>

#define BATCH 4
#define SEQ   4096
#define CDIM  1024
#define HEADS 16
#define HDIM  64
#define MROWS 16384
#define BH    64
#define NIT   32            // K=1024, BK=32

// ---------------- scratch ----------------
__device__ float g_Af[(size_t)MROWS * CDIM];        // A permuted tf32 (frag-ready)
__device__ float g_Bq[(size_t)3072 * CDIM];         // W_qkv permuted tf32
__device__ float g_Bp[(size_t)CDIM * CDIM];         // W_proj permuted tf32
__device__ float g_q[(size_t)MROWS * CDIM];
__device__ float g_k[(size_t)MROWS * CDIM];
__device__ float g_v[(size_t)MROWS * CDIM];
__device__ float g_ctx[BH * HDIM * HDIM];
__device__ float g_colsum[BH * HDIM];

__device__ __forceinline__ uint32_t smem_u32(const void* p) {
    uint32_t a;
    asm("{ .reg .u64 t; cvta.to.shared.u64 t, %1; cvt.u32.u64 %0, t; }" : "=r"(a) : "l"(p));
    return a;
}
__device__ __forceinline__ void cpa16(uint32_t saddr, const void* g) {
    asm volatile("cp.async.cg.shared.global [%0], [%1], 16;" :: "r"(saddr), "l"(g));
}
#define CPA_COMMIT() asm volatile("cp.async.commit_group;" ::: "memory")

__device__ __forceinline__ uint32_t tf32r(float f) {
    uint32_t u;
    asm("cvt.rna.tf32.f32 %0, %1;" : "=r"(u) : "f"(f));
    return u;
}
__device__ __forceinline__ void mma_tf32(float* d, const uint4 a, const uint2 b) {
    asm volatile("mma.sync.aligned.m16n8k8.row.col.f32.tf32.tf32.f32 "
        "{%0,%1,%2,%3}, {%4,%5,%6,%7}, {%8,%9}, {%0,%1,%2,%3};"
        : "+f"(d[0]), "+f"(d[1]), "+f"(d[2]), "+f"(d[3])
        : "r"(a.x), "r"(a.y), "r"(a.z), "r"(a.w), "r"(b.x), "r"(b.y));
}

// ---------------- TF32 GEMM (R12, proven: 128x128, BK=32, 3-stage) ----------------
#define ASTG  16384
#define STGB  32768
#define GSMEM (3 * STGB)    // 98304 -> 2 CTA/SM

__device__ __forceinline__ void load_stage(uint32_t dst,
        const float* __restrict__ A, const float* __restrict__ B,
        int it, int bmblk, int bnblk, int tid) {
    const int kb0 = it * 4;
#pragma unroll
    for (int l = 0; l < 4; l++) {
        int c = tid + l * 256;
        int mb = c >> 7, rest = c & 127;
        cpa16(dst + (uint32_t)(mb * 2048 + rest * 16),
              A + ((size_t)(bmblk + mb) * 128 + kb0) * 128 + rest * 4);
    }
#pragma unroll
    for (int l = 0; l < 4; l++) {
        int c = tid + l * 256;
        int nb = c >> 6, rest = c & 63;
        cpa16(dst + ASTG + (uint32_t)(nb * 1024 + rest * 16),
              B + ((size_t)(bnblk + nb) * 128 + kb0) * 64 + rest * 4);
    }
    CPA_COMMIT();
}

template<int MODE>
__global__ void __launch_bounds__(256)
gemm_tf32(const float* __restrict__ A, const float* __restrict__ Bm,
          const float* __restrict__ bias, float* __restrict__ Cout, int Nn)
{
    extern __shared__ char dsm[];
    const uint32_t s0 = smem_u32(dsm);

    const int tid = threadIdx.x, wid = tid >> 5, lane = tid & 31;
    const int bm = blockIdx.y * 128, bn = blockIdx.x * 128;
    const int bmblk = bm >> 4, bnblk = bn >> 3;
    const int mw = wid & 1, nw = wid >> 1;

    float acc[4][4][4];
#pragma unroll
    for (int i = 0; i < 4; i++)
#pragma unroll
        for (int j = 0; j < 4; j++)
#pragma unroll
            for (int r = 0; r < 4; r++) acc[i][j][r] = 0.f;

    load_stage(s0,        A, Bm, 0, bmblk, bnblk, tid);
    load_stage(s0 + STGB, A, Bm, 1, bmblk, bnblk, tid);

    for (int i = 0; i < NIT; i++) {
        if (i + 2 < NIT) asm volatile("cp.async.wait_group 1;" ::: "memory");
        else             asm volatile("cp.async.wait_group 0;" ::: "memory");
        __syncthreads();
        if (i + 2 < NIT)
            load_stage(s0 + ((i + 2) % 3) * STGB, A, Bm, i + 2, bmblk, bnblk, tid);

        const uint4* apw = (const uint4*)(dsm + (i % 3) * STGB) + mw * 16 * 32 + lane;
        const uint2* bpw = (const uint2*)(dsm + (i % 3) * STGB + ASTG) + nw * 16 * 32 + lane;
#pragma unroll
        for (int kc = 0; kc < 4; kc++) {
            uint4 af[4];
            uint2 bf[4];
#pragma unroll
            for (int mt = 0; mt < 4; mt++)
                af[mt] = apw[(mt * 4 + kc) * 32];
#pragma unroll
            for (int nt = 0; nt < 4; nt++)
                bf[nt] = bpw[(nt * 4 + kc) * 32];
#pragma unroll
            for (int mt = 0; mt < 4; mt++)
#pragma unroll
                for (int nt = 0; nt < 4; nt++)
                    mma_tf32(acc[mt][nt], af[mt], bf[nt]);
        }
    }

    const int mbase = mw * 64, nbase = nw * 32;
    const int r0 = lane >> 2, cpair = (lane & 3) * 2;
#pragma unroll
    for (int mt = 0; mt < 4; mt++) {
#pragma unroll
        for (int nt = 0; nt < 4; nt++) {
            int col = bn + nbase + nt * 8 + cpair;
            float bv0 = bias[col], bv1 = bias[col + 1];
            int m0 = bm + mbase + mt * 16 + r0;
            float2 v0 = make_float2(acc[mt][nt][0] + bv0, acc[mt][nt][1] + bv1);
            float2 v1 = make_float2(acc[mt][nt][2] + bv0, acc[mt][nt][3] + bv1);
            if (MODE == 0) {
                *(float2*)&Cout[(size_t)m0 * Nn + col] = v0;
                *(float2*)&Cout[(size_t)(m0 + 8) * Nn + col] = v1;
            } else {
                int s = col >> 10, rem = col & 1023;
                int h = rem >> 6, dd = rem & 63;
                float* dst = (s == 0) ? g_q : (s == 1) ? g_k : g_v;
                {
                    int b = m0 >> 12, n = m0 & 4095;
                    *(float2*)&dst[(((size_t)(b * HEADS + h) * SEQ + n) << 6) + dd] = v0;
                }
                {
                    int m1 = m0 + 8, b = m1 >> 12, n = m1 & 4095;
                    *(float2*)&dst[(((size_t)(b * HEADS + h) * SEQ + n) << 6) + dd] = v1;
                }
            }
        }
    }
}

// ---------------- merged prep (unchanged from R14) ----------------
#define PREP_A   16384
#define PREP_BQ  (PREP_A + 6144)
#define PREP_BP  (PREP_BQ + 2048)
#define PREP_Z1  (PREP_BP + 256)
#define PREP_N   (PREP_Z1 + 1)

__global__ void __launch_bounds__(256)
prep(const float* __restrict__ x, const float* __restrict__ Wq,
     const float* __restrict__ Wp)
{
    const int bx = blockIdx.x;
    const int warp = threadIdx.x >> 5, lane = threadIdx.x & 31;
    if (bx < PREP_A) {
        int w = bx * 8 + warp;
        int mb = w >> 7, kb = w & 127;
        int r = lane >> 2, c = lane & 3;
        const float* p = x + (size_t)(mb * 16) * CDIM + kb * 8;
        uint4 o;
        o.x = tf32r(p[(size_t)r * CDIM + c]);
        o.y = tf32r(p[(size_t)(r + 8) * CDIM + c]);
        o.z = tf32r(p[(size_t)r * CDIM + c + 4]);
        o.w = tf32r(p[(size_t)(r + 8) * CDIM + c + 4]);
        ((uint4*)g_Af)[((size_t)mb * 128 + kb) * 32 + lane] = o;
    } else if (bx < PREP_BQ) {
        int w = (bx - PREP_A) * 8 + warp;
        int nb = w >> 7, kb = w & 127;
        int g = lane >> 2, c = lane & 3;
        const float* p = Wq + (size_t)(kb * 8) * 3072 + nb * 8 + g;
        uint2 o;
        o.x = tf32r(p[(size_t)c * 3072]);
        o.y = tf32r(p[(size_t)(c + 4) * 3072]);
        ((uint2*)g_Bq)[((size_t)nb * 128 + kb) * 32 + lane] = o;
    } else if (bx < PREP_BP) {
        int w = (bx - PREP_BQ) * 8 + warp;
        int nb = w >> 7, kb = w & 127;
        int g = lane >> 2, c = lane & 3;
        const float* p = Wp + (size_t)(kb * 8) * CDIM + nb * 8 + g;
        uint2 o;
        o.x = tf32r(p[(size_t)c * CDIM]);
        o.y = tf32r(p[(size_t)(c + 4) * CDIM]);
        ((uint2*)g_Bp)[((size_t)nb * 128 + kb) * 32 + lane] = o;
    } else if (bx < PREP_Z1) {
        int i = (bx - PREP_BP) * 256 + threadIdx.x;
        ((float4*)g_ctx)[i] = make_float4(0.f, 0.f, 0.f, 0.f);
    } else {
        int i = threadIdx.x;
#pragma unroll
        for (int t = 0; t < 4; t++)
            ((float4*)g_colsum)[i + t * 256] = make_float4(0.f, 0.f, 0.f, 0.f);
    }
}

// ---------------- middle: exp(k)^T v + colsum via tf32 MMA (unchanged) ----------------
__global__ void __launch_bounds__(256) ctx_mma() {
    const int bh = blockIdx.y, chunk = blockIdx.x;
    const float* kp = g_k + (size_t)bh * SEQ * HDIM;
    const float* vp = g_v + (size_t)bh * SEQ * HDIM;
    __shared__ float kt[32][72], vt[32][72];
    __shared__ float csred[256];
    const int tid = threadIdx.x, warp = tid >> 5, lane = tid & 31;
    const int mt = warp >> 1;
    const int ng = (warp & 1) * 4;
    const int fr = lane >> 2, fc = lane & 3;

    float acc[4][4];
#pragma unroll
    for (int i = 0; i < 4; i++)
#pragma unroll
        for (int j = 0; j < 4; j++) acc[i][j] = 0.f;
    float csum = 0.f;
    const int n0 = chunk * 256;

    for (int t = 0; t < 8; t++) {
        __syncthreads();
        for (int i = tid; i < 2048; i += 256) {
            int r = i >> 6, c = i & 63;
            size_t g = (size_t)(n0 + t * 32 + r) * 64 + c;
            float ex = __expf(kp[g]);
            kt[r][c] = ex;
            csum += ex;
            vt[r][c] = vp[g];
        }
        __syncthreads();
#pragma unroll
        for (int ks = 0; ks < 4; ks++) {
            const int nr = ks * 8;
            uint4 af;
            af.x = tf32r(kt[nr + fc][mt * 16 + fr]);
            af.y = tf32r(kt[nr + fc][mt * 16 + fr + 8]);
            af.z = tf32r(kt[nr + fc + 4][mt * 16 + fr]);
            af.w = tf32r(kt[nr + fc + 4][mt * 16 + fr + 8]);
#pragma unroll
            for (int nt = 0; nt < 4; nt++) {
                const int e0 = (ng + nt) * 8;
                uint2 bf;
                bf.x = tf32r(vt[nr + fc][e0 + fr]);
                bf.y = tf32r(vt[nr + fc + 4][e0 + fr]);
                mma_tf32(acc[nt], af, bf);
            }
        }
    }

    const int row = lane >> 2, colp = (lane & 3) * 2;
    const int d0 = mt * 16;
#pragma unroll
    for (int nt = 0; nt < 4; nt++) {
        int e = (ng + nt) * 8 + colp;
        float* base = &g_ctx[((size_t)bh * 64 + d0 + row) * 64 + e];
        atomicAdd(base,     acc[nt][0]);
        atomicAdd(base + 1, acc[nt][1]);
        float* base2 = &g_ctx[((size_t)bh * 64 + d0 + row + 8) * 64 + e];
        atomicAdd(base2,     acc[nt][2]);
        atomicAdd(base2 + 1, acc[nt][3]);
    }
    csred[tid] = csum;
    __syncthreads();
    if (tid < 64)
        atomicAdd(&g_colsum[bh * 64 + tid],
                  csred[tid] + csred[tid + 64] + csred[tid + 128] + csred[tid + 192]);
}

// ---------------- qattend: 64-row blocks, smem-staged q, tf32 MMA ----------------
// grid (SEQ/64, BH). qs holds: q tile -> probabilities -> sout (phase-aliased).
__global__ void __launch_bounds__(256) qattend() {
    const int bh = blockIdx.y;
    const int n0 = blockIdx.x * 64;
    __shared__ float ctxs[64][72];   // B frags: banks (8*fc+fr) distinct
    __shared__ float qs[64][68];     // A frags: banks (4*fr+fc) distinct
    __shared__ float rsum[64];
    const int tid = threadIdx.x;
    const int warp = tid >> 5, lane = tid & 31;
    const int b = bh >> 4, h = bh & 15;

    if (tid < 64) rsum[tid] = 1.f / g_colsum[bh * 64 + tid];
    // q tile: 64 rows x 16 float4, coalesced, MLP=4
#pragma unroll
    for (int l = 0; l < 4; l++) {
        int idx = tid + l * 256;
        int row = idx >> 4, c4 = idx & 15;
        float4 v = *(const float4*)(g_q + ((size_t)bh * SEQ + n0 + row) * 64 + c4 * 4);
        *(float4*)&qs[row][c4 * 4] = v;
    }
    __syncthreads();
    for (int i = tid; i < 4096; i += 256) {
        int d = i >> 6, ee = i & 63;
        ctxs[d][ee] = g_ctx[((size_t)bh * 64 + d) * 64 + ee] * rsum[d];
    }

    // softmax: warp w owns rows w*8..w*8+7, in-place in qs
#pragma unroll
    for (int rr = 0; rr < 8; rr++) {
        int row = warp * 8 + rr;
        float q0 = qs[row][lane], q1 = qs[row][lane + 32];
        float mx = fmaxf(q0, q1);
#pragma unroll
        for (int o = 16; o; o >>= 1) mx = fmaxf(mx, __shfl_xor_sync(0xffffffffu, mx, o));
        float e0 = __expf(q0 - mx), e1 = __expf(q1 - mx);
        float s = e0 + e1;
#pragma unroll
        for (int o = 16; o; o >>= 1) s += __shfl_xor_sync(0xffffffffu, s, o);
        float inv = 1.f / s;
        qs[row][lane] = e0 * inv;
        qs[row][lane + 32] = e1 * inv;
    }
    __syncthreads();

    // MMA: warp -> (mt = warp>>1 rows mt*16.., ngrp = warp&1 cols ngrp*32..)
    const int mt = warp >> 1, ngrp = warp & 1;
    const int fr = lane >> 2, fc = lane & 3;
    float acc[4][4];
#pragma unroll
    for (int i = 0; i < 4; i++)
#pragma unroll
        for (int j = 0; j < 4; j++) acc[i][j] = 0.f;
#pragma unroll
    for (int ks = 0; ks < 8; ks++) {
        const int k0 = ks * 8;
        uint4 af;
        af.x = tf32r(qs[mt * 16 + fr][k0 + fc]);
        af.y = tf32r(qs[mt * 16 + fr + 8][k0 + fc]);
        af.z = tf32r(qs[mt * 16 + fr][k0 + fc + 4]);
        af.w = tf32r(qs[mt * 16 + fr + 8][k0 + fc + 4]);
#pragma unroll
        for (int nt = 0; nt < 4; nt++) {
            const int e0 = ngrp * 32 + nt * 8;
            uint2 bf;
            bf.x = tf32r(ctxs[k0 + fc][e0 + fr]);
            bf.y = tf32r(ctxs[k0 + fc + 4][e0 + fr]);
            mma_tf32(acc[nt], af, bf);
        }
    }
    __syncthreads();   // all reads of qs done; reuse as sout

    const int row = lane >> 2, colp = (lane & 3) * 2;
#pragma unroll
    for (int nt = 0; nt < 4; nt++) {
        const int e = ngrp * 32 + nt * 8 + colp;
        qs[mt * 16 + row][e] = acc[nt][0];
        qs[mt * 16 + row][e + 1] = acc[nt][1];
        qs[mt * 16 + row + 8][e] = acc[nt][2];
        qs[mt * 16 + row + 8][e + 1] = acc[nt][3];
    }
    __syncthreads();

    // permuted tf32 write: 32 tiles (4 mblk x 8 kblk), 4 per warp
    const int mblk0 = (b * SEQ + n0) >> 4;
    const int r = lane >> 2, c = lane & 3;
#pragma unroll
    for (int t = 0; t < 4; t++) {
        int idx = warp * 4 + t;
        int mb = idx >> 3, kb = idx & 7;
        uint4 o;
        o.x = tf32r(qs[mb * 16 + r][kb * 8 + c]);
        o.y = tf32r(qs[mb * 16 + r + 8][kb * 8 + c]);
        o.z = tf32r(qs[mb * 16 + r][kb * 8 + c + 4]);
        o.w = tf32r(qs[mb * 16 + r + 8][kb * 8 + c + 4]);
        ((uint4*)g_Af)[((size_t)(mblk0 + mb) * 128 + (h * 8 + kb)) * 32 + lane] = o;
    }
}

// ---------------------------------------------------------------------------
extern "C" void kernel_launch(void* const* d_in, const int* in_sizes, int n_in,
                              void* d_out, int out_size) {
    const float* x      = (const float*)d_in[0];
    const float* W_qkv  = (const float*)d_in[1];
    const float* b_qkv  = (const float*)d_in[2];
    const float* W_proj = (const float*)d_in[3];
    const float* b_proj = (const float*)d_in[4];
    float* out = (float*)d_out;

    void *paf, *pbq, *pbp;
    cudaGetSymbolAddress(&paf, g_Af);
    cudaGetSymbolAddress(&pbq, g_Bq);
    cudaGetSymbolAddress(&pbp, g_Bp);

    cudaFuncSetAttribute(gemm_tf32<0>, cudaFuncAttributeMaxDynamicSharedMemorySize, GSMEM);
    cudaFuncSetAttribute(gemm_tf32<1>, cudaFuncAttributeMaxDynamicSharedMemorySize, GSMEM);

    prep<<<PREP_N, 256>>>(x, W_qkv, W_proj);

    gemm_tf32<1><<<dim3(3072 / 128, MROWS / 128), 256, GSMEM>>>(
        (const float*)paf, (const float*)pbq, b_qkv, nullptr, 3072);

    ctx_mma<<<dim3(SEQ / 256, BH), 256>>>();

    qattend<<<dim3(SEQ / 64, BH), 256>>>();

    gemm_tf32<0><<<dim3(CDIM / 128, MROWS / 128), 256, GSMEM>>>(
        (const float*)paf, (const float*)pbp, b_proj, out, CDIM);
}